// round 9
// baseline (speedup 1.0000x reference)
#include <cuda_runtime.h>
#include <cuda_fp16.h>
#include <math.h>
#include <stdint.h>

#define BB 256
#define NN 256
#define DD 136
#define HH 128
#define ROWS (BB*NN)

#define K1PAD 152      // A layer-1 K stride (304B rows -> conflict-free ldmatrix)
#define K2PAD 136      // A layer-2 K stride (272B rows -> conflict-free)
#define WNS   136      // W n-stride [k][n] (272B rows -> conflict-free ldmatrix.trans)
#define NT    512      // 16 warps

__device__ float g_scores[ROWS];

// ---------------- smem layout ----------------
#define A_BYTES  (128 * K1PAD * 2)          // 38912
#define W1_BYTES (144 * WNS * 2)            // 39168 (rows 136..143 zeroed)
#define W2_BYTES (128 * WNS * 2)            // 34816
#define OFF_A    0
#define OFF_W1   (A_BYTES)                  // 38912
#define OFF_W2   (OFF_W1 + W1_BYTES)        // 78080
#define OFF_B1   (OFF_W2 + W2_BYTES)        // 112896
#define OFF_B2   (OFF_B1 + 512)
#define OFF_W3   (OFF_B2 + 512)
#define OFF_RED  (OFF_W3 + 512)
#define SMEM_BYTES (OFF_RED + 1024)         // 115456

__device__ __forceinline__ uint32_t smem_u32(const void* p) {
    uint32_t a;
    asm("{ .reg .u64 t; cvta.to.shared.u64 t, %1; cvt.u32.u64 %0, t; }" : "=r"(a) : "l"(p));
    return a;
}
__device__ __forceinline__ void ldsm_x4(uint32_t* r, uint32_t addr) {
    asm volatile("ldmatrix.sync.aligned.m8n8.x4.shared.b16 {%0,%1,%2,%3}, [%4];"
        : "=r"(r[0]), "=r"(r[1]), "=r"(r[2]), "=r"(r[3]) : "r"(addr));
}
__device__ __forceinline__ void ldsm_x4_t(uint32_t* r, uint32_t addr) {
    asm volatile("ldmatrix.sync.aligned.m8n8.x4.trans.shared.b16 {%0,%1,%2,%3}, [%4];"
        : "=r"(r[0]), "=r"(r[1]), "=r"(r[2]), "=r"(r[3]) : "r"(addr));
}
__device__ __forceinline__ void mma16816(float* d, const uint32_t* a, uint32_t b0, uint32_t b1) {
    asm volatile("mma.sync.aligned.m16n8k16.row.col.f32.f16.f16.f32 "
        "{%0,%1,%2,%3}, {%4,%5,%6,%7}, {%8,%9}, {%0,%1,%2,%3};"
        : "+f"(d[0]), "+f"(d[1]), "+f"(d[2]), "+f"(d[3])
        : "r"(a[0]), "r"(a[1]), "r"(a[2]), "r"(a[3]), "r"(b0), "r"(b1));
}
__device__ __forceinline__ uint32_t pack_h2(float x, float y) {
    __half h0 = __float2half_rn(x), h1 = __float2half_rn(y);
    return ((uint32_t)__half_as_ushort(h1) << 16) | __half_as_ushort(h0);
}

// ---------------- fused MLP, fp16 MMA, W staged [k][n] + ldmatrix.trans ----------------
__global__ __launch_bounds__(NT, 1)
void mlp_mma(const float* __restrict__ feat,
             const float* __restrict__ W1, const float* __restrict__ b1,
             const float* __restrict__ W2, const float* __restrict__ b2,
             const float* __restrict__ W3, const float* __restrict__ b3)
{
    extern __shared__ char smem[];
    __half* A   = (__half*)(smem + OFF_A);
    __half* W1S = (__half*)(smem + OFF_W1);
    __half* W2S = (__half*)(smem + OFF_W2);
    float* sB1 = (float*)(smem + OFF_B1);
    float* sB2 = (float*)(smem + OFF_B2);
    float* sW3 = (float*)(smem + OFF_W3);
    float* red = (float*)(smem + OFF_RED);

    const int tid  = threadIdx.x;
    const int lane = tid & 31;
    const int wid  = tid >> 5;
    const int m0    = (wid >> 1) * 16;
    const int nside = (wid & 1) * 64;
    const long row0 = (long)blockIdx.x * 128;

    const uint32_t uA  = smem_u32(smem + OFF_A);
    const uint32_t uW1 = smem_u32(smem + OFF_W1);
    const uint32_t uW2 = smem_u32(smem + OFF_W2);

    // A-side ldmatrix address components (row-major [m][k])
    const int a_row = m0 + (lane & 7) + ((lane >> 3) & 1) * 8;
    const int a_kof = (lane >> 4) * 8;
    // W-side ldmatrix.trans address components ([k][n] memory)
    const int w_krow = (lane & 7) + ((lane >> 3) & 1) * 8;
    const int w_ncol = (lane >> 4) * 8;

    // ---- stage biases / W3 ----
    if (tid < 128) { sB1[tid] = b1[tid]; sB2[tid] = b2[tid]; sW3[tid] = W3[tid]; }
    const float b3v = __ldg(b3);

    // ---- stage W1 [k][n] fp32 -> fp16, no transpose (17 iters) ----
    for (int i = tid; i < 136 * 64; i += NT) {
        const int k = i >> 6, n2 = (i & 63) * 2;
        float2 v = *(const float2*)(W1 + k * HH + n2);
        *(uint32_t*)(W1S + k * WNS + n2) = pack_h2(v.x, v.y);
    }
    // zero W1 rows k = 136..143
    for (int i = tid; i < 8 * 68; i += NT) {
        const int k = 136 + i / 68, n2 = (i % 68) * 2;
        *(uint32_t*)(W1S + k * WNS + n2) = 0;
    }
    // ---- stage W2 (16 iters) ----
    for (int i = tid; i < 128 * 64; i += NT) {
        const int k = i >> 6, n2 = (i & 63) * 2;
        float2 v = *(const float2*)(W2 + k * HH + n2);
        *(uint32_t*)(W2S + k * WNS + n2) = pack_h2(v.x, v.y);
    }

    // ---- stage features -> fp16, [m][k] stride K1PAD ----
    {
        const int r  = tid >> 2;        // row 0..127
        const int c4 = tid & 3;         // pair-lane
        const float* fb = feat + row0 * DD + (long)r * DD + 2 * c4;
        float2 v[17];
        #pragma unroll
        for (int it = 0; it < 17; it++) v[it] = *(const float2*)(fb + 8 * it);
        #pragma unroll
        for (int it = 0; it < 17; it++) {
            const int p = c4 + 4 * it;          // 0..67
            *(uint32_t*)(A + r * K1PAD + 2 * p) = pack_h2(v[it].x, v[it].y);
        }
        // zero pad k = 136..151
        *(uint32_t*)(A + r * K1PAD + 2 * (68 + c4)) = 0;
        *(uint32_t*)(A + r * K1PAD + 2 * (72 + c4)) = 0;
    }
    __syncthreads();

    float acc[8][4];
    #pragma unroll
    for (int t = 0; t < 8; t++)
        #pragma unroll
        for (int q = 0; q < 4; q++) acc[t][q] = 0.f;

    // ---- layer 1: 9 ksteps ----
    #pragma unroll
    for (int ks = 0; ks < 9; ks++) {
        const int k0 = ks * 16;
        uint32_t a[4];
        ldsm_x4(a, uA + (a_row * K1PAD + k0 + a_kof) * 2);
        #pragma unroll
        for (int np = 0; np < 4; np++) {
            const int n0 = nside + np * 16;
            uint32_t w[4];
            ldsm_x4_t(w, uW1 + ((k0 + w_krow) * WNS + n0 + w_ncol) * 2);
            mma16816(acc[2*np],   a, w[0], w[1]);
            mma16816(acc[2*np+1], a, w[2], w[3]);
        }
    }
    __syncthreads();

    // ---- epilogue 1: relu(+b1) -> fp16 into A, stride K2PAD ----
    {
        const int rA = m0 + (lane >> 2);
        #pragma unroll
        for (int nt = 0; nt < 8; nt++) {
            const int c = nside + nt * 8 + (lane & 3) * 2;
            float v0 = fmaxf(acc[nt][0] + sB1[c],     0.f);
            float v1 = fmaxf(acc[nt][1] + sB1[c + 1], 0.f);
            float v2 = fmaxf(acc[nt][2] + sB1[c],     0.f);
            float v3 = fmaxf(acc[nt][3] + sB1[c + 1], 0.f);
            *(uint32_t*)(A + rA * K2PAD + c)       = pack_h2(v0, v1);
            *(uint32_t*)(A + (rA + 8) * K2PAD + c) = pack_h2(v2, v3);
        }
    }
    __syncthreads();

    #pragma unroll
    for (int t = 0; t < 8; t++)
        #pragma unroll
        for (int q = 0; q < 4; q++) acc[t][q] = 0.f;

    // ---- layer 2: 8 ksteps ----
    #pragma unroll
    for (int ks = 0; ks < 8; ks++) {
        const int k0 = ks * 16;
        uint32_t a[4];
        ldsm_x4(a, uA + (a_row * K2PAD + k0 + a_kof) * 2);
        #pragma unroll
        for (int np = 0; np < 4; np++) {
            const int n0 = nside + np * 16;
            uint32_t w[4];
            ldsm_x4_t(w, uW2 + ((k0 + w_krow) * WNS + n0 + w_ncol) * 2);
            mma16816(acc[2*np],   a, w[0], w[1]);
            mma16816(acc[2*np+1], a, w[2], w[3]);
        }
    }

    // ---- epilogue 2: relu(+b2) . W3, reduce to scores ----
    {
        float pl = 0.f, ph = 0.f;
        #pragma unroll
        for (int nt = 0; nt < 8; nt++) {
            const int c = nside + nt * 8 + (lane & 3) * 2;
            pl = fmaf(fmaxf(acc[nt][0] + sB2[c],     0.f), sW3[c],     pl);
            pl = fmaf(fmaxf(acc[nt][1] + sB2[c + 1], 0.f), sW3[c + 1], pl);
            ph = fmaf(fmaxf(acc[nt][2] + sB2[c],     0.f), sW3[c],     ph);
            ph = fmaf(fmaxf(acc[nt][3] + sB2[c + 1], 0.f), sW3[c + 1], ph);
        }
        pl += __shfl_xor_sync(0xFFFFFFFF, pl, 1);
        pl += __shfl_xor_sync(0xFFFFFFFF, pl, 2);
        ph += __shfl_xor_sync(0xFFFFFFFF, ph, 1);
        ph += __shfl_xor_sync(0xFFFFFFFF, ph, 2);
        if ((lane & 3) == 0) {
            const int r = m0 + (lane >> 2);
            red[r * 2 + (wid & 1)]       = pl;
            red[(r + 8) * 2 + (wid & 1)] = ph;
        }
    }
    __syncthreads();
    if (tid < 128)
        g_scores[row0 + tid] = red[tid * 2] + red[tid * 2 + 1] + b3v;
}

// ---------------- lambda kernel: 2 blocks/batch, j-loop split 2 ways ----------------
__global__ __launch_bounds__(256, 8)
void lambda_kernel(const int* __restrict__ labels, float* __restrict__ out)
{
    __shared__ float4 elg[NN];       // {exp(s), 1+log2(1+s), 2^label, 0}
    __shared__ float  part[128];

    const int bid   = blockIdx.x;        // 0..511
    const int batch = bid >> 1;
    const int ihalf = bid & 1;
    const int tid   = threadIdx.x;       // 0..255
    const int il    = tid & 127;
    const int jh    = tid >> 7;

    {
        float s = g_scores[batch * NN + tid];
        int   l = labels[batch * NN + tid];
        elg[tid] = make_float4(expf(s), 1.0f + log2f(1.0f + s), exp2f((float)l), 0.f);
    }
    __syncthreads();

    const int i = ihalf * 128 + il;
    const float4 me = elg[i];
    const float ei = me.x, Mi = me.y, gi = me.z;

    float acc0 = 0.f, acc1 = 0.f;
    const int j0 = jh * 128;
    #pragma unroll 4
    for (int j = 0; j < 128; j += 2) {
        float4 va = elg[j0 + j];
        float4 vb = elg[j0 + j + 1];
        float sga = gi - va.z;
        float sgb = gi - vb.z;
        float ta = (sga > 0.f) ? ei : va.x;
        float tb = (sgb > 0.f) ? ei : vb.x;
        acc0 += __fdividef(sga * ta, fabsf(fmaxf(Mi, va.y)) * (ei + va.x));
        acc1 += __fdividef(sgb * tb, fabsf(fmaxf(Mi, vb.y)) * (ei + vb.x));
    }
    float acc = acc0 + acc1;
    if (jh == 0) part[il] = acc;
    __syncthreads();
    if (jh == 1)
        out[batch * NN + i] = 0.5f * (acc + part[il]);
}

extern "C" void kernel_launch(void* const* d_in, const int* in_sizes, int n_in,
                              void* d_out, int out_size)
{
    const float* feat   = (const float*)d_in[0];
    const int*   labels = (const int*)d_in[1];
    const float* W1 = (const float*)d_in[2];
    const float* b1 = (const float*)d_in[3];
    const float* W2 = (const float*)d_in[4];
    const float* b2 = (const float*)d_in[5];
    const float* W3 = (const float*)d_in[6];
    const float* b3 = (const float*)d_in[7];
    float* out = (float*)d_out;

    static bool attr_set = false;
    if (!attr_set) {
        cudaFuncSetAttribute(mlp_mma, cudaFuncAttributeMaxDynamicSharedMemorySize,
                             (int)SMEM_BYTES);
        attr_set = true;
    }

    mlp_mma<<<ROWS / 128, NT, SMEM_BYTES>>>(feat, W1, b1, W2, b2, W3, b3);
    lambda_kernel<<<2 * BB, 256>>>(labels, out);
}

// round 10
// speedup vs baseline: 1.4394x; 1.4394x over previous
#include <cuda_runtime.h>
#include <cuda_fp16.h>
#include <math.h>
#include <stdint.h>

#define BB 256
#define NN 256
#define DD 136
#define HH 128
#define ROWS (BB*NN)

#define K1PAD 152      // layer-1 K stride (304B rows -> conflict-free ldmatrix)
#define K2PAD 136      // layer-2 K stride (272B rows -> conflict-free)
#define NT    512      // 16 warps

// ---------------- scratch globals ----------------
__device__ float g_scores[ROWS];
__device__ __align__(16) __half g_W1t[HH * K1PAD];   // fp16, transposed [n][k], zero-padded
__device__ __align__(16) __half g_W2t[HH * K2PAD];

// ---------------- smem layout ----------------
#define A_BYTES  (128 * K1PAD * 2)          // 38912
#define W1_BYTES (128 * K1PAD * 2)          // 38912
#define W2_BYTES (128 * K2PAD * 2)          // 34816
#define OFF_A    0
#define OFF_W1   (A_BYTES)                  // 38912
#define OFF_W2   (OFF_W1 + W1_BYTES)        // 77824
#define OFF_B1   (OFF_W2 + W2_BYTES)        // 112640
#define OFF_B2   (OFF_B1 + 512)
#define OFF_W3   (OFF_B2 + 512)
#define OFF_RED  (OFF_W3 + 512)
#define SMEM_BYTES (OFF_RED + 1024)         // 115200

__device__ __forceinline__ uint32_t smem_u32(const void* p) {
    uint32_t a;
    asm("{ .reg .u64 t; cvta.to.shared.u64 t, %1; cvt.u32.u64 %0, t; }" : "=r"(a) : "l"(p));
    return a;
}
__device__ __forceinline__ void cp_async16(uint32_t dst, const void* src) {
    asm volatile("cp.async.cg.shared.global [%0], [%1], 16;" :: "r"(dst), "l"(src));
}
#define CP_COMMIT() asm volatile("cp.async.commit_group;" ::: "memory")
#define CP_WAIT0()  asm volatile("cp.async.wait_group 0;" ::: "memory")

__device__ __forceinline__ void ldsm_x4(uint32_t* r, uint32_t addr) {
    asm volatile("ldmatrix.sync.aligned.m8n8.x4.shared.b16 {%0,%1,%2,%3}, [%4];"
        : "=r"(r[0]), "=r"(r[1]), "=r"(r[2]), "=r"(r[3]) : "r"(addr));
}
__device__ __forceinline__ void mma16816(float* d, const uint32_t* a, uint32_t b0, uint32_t b1) {
    asm volatile("mma.sync.aligned.m16n8k16.row.col.f32.f16.f16.f32 "
        "{%0,%1,%2,%3}, {%4,%5,%6,%7}, {%8,%9}, {%0,%1,%2,%3};"
        : "+f"(d[0]), "+f"(d[1]), "+f"(d[2]), "+f"(d[3])
        : "r"(a[0]), "r"(a[1]), "r"(a[2]), "r"(a[3]), "r"(b0), "r"(b1));
}
__device__ __forceinline__ uint32_t pack_h2(float x, float y) {
    __half h0 = __float2half_rn(x), h1 = __float2half_rn(y);
    return ((uint32_t)__half_as_ushort(h1) << 16) | __half_as_ushort(h0);
}

// ---------------- weight prep: fp16 round + transpose, float4-vectorized ----------------
__global__ void prep_w(const float* __restrict__ W1, const float* __restrict__ W2) {
    int idx = blockIdx.x * 256 + threadIdx.x;
    if (idx < 152 * 32) {                       // W1: k in [0,152), 32 n-quads
        int k = idx >> 5, nq = (idx & 31) * 4;
        float4 v = (k < DD) ? *(const float4*)(W1 + k * HH + nq)
                            : make_float4(0.f, 0.f, 0.f, 0.f);
        g_W1t[(nq + 0) * K1PAD + k] = __float2half_rn(v.x);
        g_W1t[(nq + 1) * K1PAD + k] = __float2half_rn(v.y);
        g_W1t[(nq + 2) * K1PAD + k] = __float2half_rn(v.z);
        g_W1t[(nq + 3) * K1PAD + k] = __float2half_rn(v.w);
        return;
    }
    int idx2 = idx - 152 * 32;
    if (idx2 < 128 * 32) {                      // W2: k in [0,128)
        int k = idx2 >> 5, nq = (idx2 & 31) * 4;
        float4 v = *(const float4*)(W2 + k * HH + nq);
        g_W2t[(nq + 0) * K2PAD + k] = __float2half_rn(v.x);
        g_W2t[(nq + 1) * K2PAD + k] = __float2half_rn(v.y);
        g_W2t[(nq + 2) * K2PAD + k] = __float2half_rn(v.z);
        g_W2t[(nq + 3) * K2PAD + k] = __float2half_rn(v.w);
    }
}

// ---------------- fused MLP, warp-level fp16 MMA (R8-identical) ----------------
__global__ __launch_bounds__(NT, 1)
void mlp_mma(const float* __restrict__ feat,
             const float* __restrict__ b1, const float* __restrict__ b2,
             const float* __restrict__ W3, const float* __restrict__ b3)
{
    extern __shared__ char smem[];
    __half* A  = (__half*)(smem + OFF_A);
    float* sB1 = (float*)(smem + OFF_B1);
    float* sB2 = (float*)(smem + OFF_B2);
    float* sW3 = (float*)(smem + OFF_W3);
    float* red = (float*)(smem + OFF_RED);

    const int tid  = threadIdx.x;
    const int lane = tid & 31;
    const int wid  = tid >> 5;
    const int m0    = (wid >> 1) * 16;
    const int nside = (wid & 1) * 64;
    const long row0 = (long)blockIdx.x * 128;

    const uint32_t uA  = smem_u32(smem + OFF_A);
    const uint32_t uW1 = smem_u32(smem + OFF_W1);
    const uint32_t uW2 = smem_u32(smem + OFF_W2);

    const int a_row = m0 + (lane & 7) + ((lane >> 3) & 1) * 8;
    const int a_kof = (lane >> 4) * 8;
    const int w_rof = (lane & 7) + (lane >> 4) * 8;
    const int w_kof = ((lane >> 3) & 1) * 8;

    // ---- stage 1: weight tiles via cp.async ----
    {
        const char* s;
        s = (const char*)g_W1t;
        for (int i = tid; i < W1_BYTES / 16; i += NT) cp_async16(uW1 + i * 16, s + i * 16);
        s = (const char*)g_W2t;
        for (int i = tid; i < W2_BYTES / 16; i += NT) cp_async16(uW2 + i * 16, s + i * 16);
        CP_COMMIT();
    }

    // ---- stage 2: biases / W3 ----
    if (tid < 128) { sB1[tid] = b1[tid]; sB2[tid] = b2[tid]; sW3[tid] = W3[tid]; }

    // ---- stage 3: features -> fp16 ----
    {
        const int r  = tid >> 2;
        const int c4 = tid & 3;
        const float* fb = feat + row0 * DD + (long)r * DD + 2 * c4;
        float2 v[17];
        #pragma unroll
        for (int it = 0; it < 17; it++) v[it] = *(const float2*)(fb + 8 * it);
        #pragma unroll
        for (int it = 0; it < 17; it++) {
            const int p = c4 + 4 * it;
            *(uint32_t*)(A + r * K1PAD + 2 * p) = pack_h2(v[it].x, v[it].y);
        }
        *(uint32_t*)(A + r * K1PAD + 2 * (68 + c4)) = 0;
        *(uint32_t*)(A + r * K1PAD + 2 * (72 + c4)) = 0;
    }
    CP_WAIT0();
    __syncthreads();

    float acc[8][4];
    #pragma unroll
    for (int t = 0; t < 8; t++)
        #pragma unroll
        for (int q = 0; q < 4; q++) acc[t][q] = 0.f;

    // ---- layer 1: 9 ksteps ----
    #pragma unroll
    for (int ks = 0; ks < 9; ks++) {
        const int k0 = ks * 16;
        uint32_t a[4];
        ldsm_x4(a, uA + (a_row * K1PAD + k0 + a_kof) * 2);
        #pragma unroll
        for (int np = 0; np < 4; np++) {
            const int n0 = nside + np * 16;
            uint32_t w[4];
            ldsm_x4(w, uW1 + ((n0 + w_rof) * K1PAD + k0 + w_kof) * 2);
            mma16816(acc[2*np],   a, w[0], w[1]);
            mma16816(acc[2*np+1], a, w[2], w[3]);
        }
    }
    __syncthreads();

    // ---- epilogue 1: relu(+b1) -> fp16 into A, stride K2PAD ----
    {
        const int rA = m0 + (lane >> 2);
        #pragma unroll
        for (int nt = 0; nt < 8; nt++) {
            const int c = nside + nt * 8 + (lane & 3) * 2;
            float v0 = fmaxf(acc[nt][0] + sB1[c],     0.f);
            float v1 = fmaxf(acc[nt][1] + sB1[c + 1], 0.f);
            float v2 = fmaxf(acc[nt][2] + sB1[c],     0.f);
            float v3 = fmaxf(acc[nt][3] + sB1[c + 1], 0.f);
            *(uint32_t*)(A + rA * K2PAD + c)       = pack_h2(v0, v1);
            *(uint32_t*)(A + (rA + 8) * K2PAD + c) = pack_h2(v2, v3);
        }
    }
    __syncthreads();

    #pragma unroll
    for (int t = 0; t < 8; t++)
        #pragma unroll
        for (int q = 0; q < 4; q++) acc[t][q] = 0.f;

    // ---- layer 2: 8 ksteps ----
    #pragma unroll
    for (int ks = 0; ks < 8; ks++) {
        const int k0 = ks * 16;
        uint32_t a[4];
        ldsm_x4(a, uA + (a_row * K2PAD + k0 + a_kof) * 2);
        #pragma unroll
        for (int np = 0; np < 4; np++) {
            const int n0 = nside + np * 16;
            uint32_t w[4];
            ldsm_x4(w, uW2 + ((n0 + w_rof) * K2PAD + k0 + w_kof) * 2);
            mma16816(acc[2*np],   a, w[0], w[1]);
            mma16816(acc[2*np+1], a, w[2], w[3]);
        }
    }

    // ---- epilogue 2: relu(+b2) . W3, reduce to scores ----
    {
        float pl = 0.f, ph = 0.f;
        #pragma unroll
        for (int nt = 0; nt < 8; nt++) {
            const int c = nside + nt * 8 + (lane & 3) * 2;
            pl = fmaf(fmaxf(acc[nt][0] + sB2[c],     0.f), sW3[c],     pl);
            pl = fmaf(fmaxf(acc[nt][1] + sB2[c + 1], 0.f), sW3[c + 1], pl);
            ph = fmaf(fmaxf(acc[nt][2] + sB2[c],     0.f), sW3[c],     ph);
            ph = fmaf(fmaxf(acc[nt][3] + sB2[c + 1], 0.f), sW3[c + 1], ph);
        }
        pl += __shfl_xor_sync(0xFFFFFFFF, pl, 1);
        pl += __shfl_xor_sync(0xFFFFFFFF, pl, 2);
        ph += __shfl_xor_sync(0xFFFFFFFF, ph, 1);
        ph += __shfl_xor_sync(0xFFFFFFFF, ph, 2);
        if ((lane & 3) == 0) {
            const int r = m0 + (lane >> 2);
            red[r * 2 + (wid & 1)]       = pl;
            red[(r + 8) * 2 + (wid & 1)] = ph;
        }
    }
    __syncthreads();
    if (tid < 128)
        g_scores[row0 + tid] = red[tid * 2] + red[tid * 2 + 1] + __ldg(b3);
}

// ---------------- lambda kernel: 4 blocks/batch, j split 4 ways ----------------
__global__ __launch_bounds__(256, 8)
void lambda_kernel(const int* __restrict__ labels, float* __restrict__ out)
{
    __shared__ float4 elg[NN];       // {exp(s), 1+log2(1+s), 2^label, 0}
    __shared__ float  part[256];

    const int bid   = blockIdx.x;        // 0..1023
    const int batch = bid >> 2;
    const int iq    = bid & 3;           // i-quarter
    const int tid   = threadIdx.x;       // 0..255
    const int il    = tid & 63;          // i within quarter
    const int jh    = tid >> 6;          // j-quarter 0..3

    {
        float s = g_scores[batch * NN + tid];
        int   l = labels[batch * NN + tid];
        elg[tid] = make_float4(expf(s), 1.0f + log2f(1.0f + s), exp2f((float)l), 0.f);
    }
    __syncthreads();

    const int i = iq * 64 + il;
    const float4 me = elg[i];
    const float ei = me.x, Mi = me.y, gi = me.z;

    float acc0 = 0.f, acc1 = 0.f;
    const int j0 = jh * 64;
    #pragma unroll 4
    for (int j = 0; j < 64; j += 2) {
        float4 va = elg[j0 + j];
        float4 vb = elg[j0 + j + 1];
        float sga = gi - va.z;
        float sgb = gi - vb.z;
        float ta = (sga > 0.f) ? ei : va.x;
        float tb = (sgb > 0.f) ? ei : vb.x;
        acc0 += __fdividef(sga * ta, fabsf(fmaxf(Mi, va.y)) * (ei + va.x));
        acc1 += __fdividef(sgb * tb, fabsf(fmaxf(Mi, vb.y)) * (ei + vb.x));
    }
    part[tid] = acc0 + acc1;
    __syncthreads();
    if (tid < 64)
        out[batch * NN + iq * 64 + tid] =
            0.5f * (part[tid] + part[tid + 64] + part[tid + 128] + part[tid + 192]);
}

extern "C" void kernel_launch(void* const* d_in, const int* in_sizes, int n_in,
                              void* d_out, int out_size)
{
    const float* feat   = (const float*)d_in[0];
    const int*   labels = (const int*)d_in[1];
    const float* W1 = (const float*)d_in[2];
    const float* b1 = (const float*)d_in[3];
    const float* W2 = (const float*)d_in[4];
    const float* b2 = (const float*)d_in[5];
    const float* W3 = (const float*)d_in[6];
    const float* b3 = (const float*)d_in[7];
    float* out = (float*)d_out;

    static bool attr_set = false;
    if (!attr_set) {
        cudaFuncSetAttribute(mlp_mma, cudaFuncAttributeMaxDynamicSharedMemorySize,
                             (int)SMEM_BYTES);
        attr_set = true;
    }

    prep_w<<<(152 * 32 + 128 * 32 + 255) / 256, 256>>>(W1, W2);
    mlp_mma<<<ROWS / 128, NT, SMEM_BYTES>>>(feat, b1, b2, W3, b3);
    lambda_kernel<<<4 * BB, 256>>>(labels, out);
}

// round 11
// speedup vs baseline: 1.6449x; 1.1427x over previous
#include <cuda_runtime.h>
#include <cuda_fp16.h>
#include <math.h>
#include <stdint.h>

#define BB 256
#define NN 256
#define DD 136
#define HH 128
#define ROWS (BB*NN)

#define K1PAD 152      // layer-1 K stride (304B rows -> conflict-free ldmatrix)
#define K2PAD 136      // layer-2 K stride (272B rows -> conflict-free)
#define TM    64       // rows per CTA
#define NT    256      // 8 warps

// ---------------- scratch globals ----------------
__device__ float g_scores[ROWS];
__device__ __align__(16) __half g_W1t[HH * K1PAD];   // fp16, transposed [n][k], zero-padded
__device__ __align__(16) __half g_W2t[HH * K2PAD];

// ---------------- smem layout ----------------
#define A_BYTES  (TM * K1PAD * 2)           // 19456
#define W1_BYTES (128 * K1PAD * 2)          // 38912
#define W2_BYTES (128 * K2PAD * 2)          // 34816
#define OFF_A    0
#define OFF_W1   (A_BYTES)                  // 19456
#define OFF_W2   (OFF_W1 + W1_BYTES)        // 58368
#define OFF_B1   (OFF_W2 + W2_BYTES)        // 93184
#define OFF_B2   (OFF_B1 + 512)
#define OFF_W3   (OFF_B2 + 512)
#define OFF_RED  (OFF_W3 + 512)
#define SMEM_BYTES (OFF_RED + 512)          // 95232  (x2 CTAs = 190464 < 227KB)

__device__ __forceinline__ uint32_t smem_u32(const void* p) {
    uint32_t a;
    asm("{ .reg .u64 t; cvta.to.shared.u64 t, %1; cvt.u32.u64 %0, t; }" : "=r"(a) : "l"(p));
    return a;
}
__device__ __forceinline__ void cp_async16(uint32_t dst, const void* src) {
    asm volatile("cp.async.cg.shared.global [%0], [%1], 16;" :: "r"(dst), "l"(src));
}
#define CP_COMMIT() asm volatile("cp.async.commit_group;" ::: "memory")
#define CP_WAIT0()  asm volatile("cp.async.wait_group 0;" ::: "memory")

__device__ __forceinline__ void ldsm_x4(uint32_t* r, uint32_t addr) {
    asm volatile("ldmatrix.sync.aligned.m8n8.x4.shared.b16 {%0,%1,%2,%3}, [%4];"
        : "=r"(r[0]), "=r"(r[1]), "=r"(r[2]), "=r"(r[3]) : "r"(addr));
}
__device__ __forceinline__ void mma16816(float* d, const uint32_t* a, uint32_t b0, uint32_t b1) {
    asm volatile("mma.sync.aligned.m16n8k16.row.col.f32.f16.f16.f32 "
        "{%0,%1,%2,%3}, {%4,%5,%6,%7}, {%8,%9}, {%0,%1,%2,%3};"
        : "+f"(d[0]), "+f"(d[1]), "+f"(d[2]), "+f"(d[3])
        : "r"(a[0]), "r"(a[1]), "r"(a[2]), "r"(a[3]), "r"(b0), "r"(b1));
}
__device__ __forceinline__ uint32_t pack_h2(float x, float y) {
    __half h0 = __float2half_rn(x), h1 = __float2half_rn(y);
    return ((uint32_t)__half_as_ushort(h1) << 16) | __half_as_ushort(h0);
}

// ---------------- weight prep: fp16 round + transpose, float4-vectorized ----------------
__global__ void prep_w(const float* __restrict__ W1, const float* __restrict__ W2) {
    int idx = blockIdx.x * 256 + threadIdx.x;
    if (idx < 152 * 32) {                       // W1: k in [0,152), 32 n-quads
        int k = idx >> 5, nq = (idx & 31) * 4;
        float4 v = (k < DD) ? *(const float4*)(W1 + k * HH + nq)
                            : make_float4(0.f, 0.f, 0.f, 0.f);
        g_W1t[(nq + 0) * K1PAD + k] = __float2half_rn(v.x);
        g_W1t[(nq + 1) * K1PAD + k] = __float2half_rn(v.y);
        g_W1t[(nq + 2) * K1PAD + k] = __float2half_rn(v.z);
        g_W1t[(nq + 3) * K1PAD + k] = __float2half_rn(v.w);
        return;
    }
    int idx2 = idx - 152 * 32;
    if (idx2 < 128 * 32) {                      // W2: k in [0,128)
        int k = idx2 >> 5, nq = (idx2 & 31) * 4;
        float4 v = *(const float4*)(W2 + k * HH + nq);
        g_W2t[(nq + 0) * K2PAD + k] = __float2half_rn(v.x);
        g_W2t[(nq + 1) * K2PAD + k] = __float2half_rn(v.y);
        g_W2t[(nq + 2) * K2PAD + k] = __float2half_rn(v.z);
        g_W2t[(nq + 3) * K2PAD + k] = __float2half_rn(v.w);
    }
}

// ---------------- fused MLP, 64 rows/CTA, 2 CTAs/SM ----------------
__global__ __launch_bounds__(NT, 2)
void mlp_mma(const float* __restrict__ feat,
             const float* __restrict__ b1, const float* __restrict__ b2,
             const float* __restrict__ W3, const float* __restrict__ b3)
{
    extern __shared__ char smem[];
    __half* A  = (__half*)(smem + OFF_A);
    float* sB1 = (float*)(smem + OFF_B1);
    float* sB2 = (float*)(smem + OFF_B2);
    float* sW3 = (float*)(smem + OFF_W3);
    float* red = (float*)(smem + OFF_RED);

    const int tid  = threadIdx.x;
    const int lane = tid & 31;
    const int wid  = tid >> 5;                 // 0..7
    const int m0    = (wid >> 1) * 16;         // 0,16,32,48
    const int nside = (wid & 1) * 64;
    const long row0 = (long)blockIdx.x * TM;

    const uint32_t uA  = smem_u32(smem + OFF_A);
    const uint32_t uW1 = smem_u32(smem + OFF_W1);
    const uint32_t uW2 = smem_u32(smem + OFF_W2);

    const int a_row = m0 + (lane & 7) + ((lane >> 3) & 1) * 8;
    const int a_kof = (lane >> 4) * 8;
    const int w_rof = (lane & 7) + (lane >> 4) * 8;
    const int w_kof = ((lane >> 3) & 1) * 8;

    // ---- stage 1: weight tiles via cp.async ----
    {
        const char* s;
        s = (const char*)g_W1t;
        for (int i = tid; i < W1_BYTES / 16; i += NT) cp_async16(uW1 + i * 16, s + i * 16);
        s = (const char*)g_W2t;
        for (int i = tid; i < W2_BYTES / 16; i += NT) cp_async16(uW2 + i * 16, s + i * 16);
        CP_COMMIT();
    }

    // ---- stage 2: biases / W3 ----
    if (tid < 128) { sB1[tid] = b1[tid]; sB2[tid] = b2[tid]; sW3[tid] = W3[tid]; }
    const float b3v = __ldg(b3);

    // ---- stage 3: features -> fp16 (64 rows, 4 lanes per row) ----
    {
        const int r  = tid >> 2;        // row 0..63
        const int c4 = tid & 3;         // pair-lane
        const float* fb = feat + (row0 + r) * DD + 2 * c4;
        float2 v[17];
        #pragma unroll
        for (int it = 0; it < 17; it++) v[it] = *(const float2*)(fb + 8 * it);
        #pragma unroll
        for (int it = 0; it < 17; it++) {
            const int p = c4 + 4 * it;          // 0..67
            *(uint32_t*)(A + r * K1PAD + 2 * p) = pack_h2(v[it].x, v[it].y);
        }
        // zero pad k = 136..151
        *(uint32_t*)(A + r * K1PAD + 2 * (68 + c4)) = 0;
        *(uint32_t*)(A + r * K1PAD + 2 * (72 + c4)) = 0;
    }
    CP_WAIT0();
    __syncthreads();

    float acc[8][4];
    #pragma unroll
    for (int t = 0; t < 8; t++)
        #pragma unroll
        for (int q = 0; q < 4; q++) acc[t][q] = 0.f;

    // ---- layer 1: 9 ksteps ----
    #pragma unroll
    for (int ks = 0; ks < 9; ks++) {
        const int k0 = ks * 16;
        uint32_t a[4];
        ldsm_x4(a, uA + (a_row * K1PAD + k0 + a_kof) * 2);
        #pragma unroll
        for (int np = 0; np < 4; np++) {
            const int n0 = nside + np * 16;
            uint32_t w[4];
            ldsm_x4(w, uW1 + ((n0 + w_rof) * K1PAD + k0 + w_kof) * 2);
            mma16816(acc[2*np],   a, w[0], w[1]);
            mma16816(acc[2*np+1], a, w[2], w[3]);
        }
    }
    __syncthreads();

    // ---- epilogue 1: relu(+b1) -> fp16 into A, stride K2PAD ----
    {
        const int rA = m0 + (lane >> 2);
        #pragma unroll
        for (int nt = 0; nt < 8; nt++) {
            const int c = nside + nt * 8 + (lane & 3) * 2;
            float v0 = fmaxf(acc[nt][0] + sB1[c],     0.f);
            float v1 = fmaxf(acc[nt][1] + sB1[c + 1], 0.f);
            float v2 = fmaxf(acc[nt][2] + sB1[c],     0.f);
            float v3 = fmaxf(acc[nt][3] + sB1[c + 1], 0.f);
            *(uint32_t*)(A + rA * K2PAD + c)       = pack_h2(v0, v1);
            *(uint32_t*)(A + (rA + 8) * K2PAD + c) = pack_h2(v2, v3);
        }
    }
    __syncthreads();

    #pragma unroll
    for (int t = 0; t < 8; t++)
        #pragma unroll
        for (int q = 0; q < 4; q++) acc[t][q] = 0.f;

    // ---- layer 2: 8 ksteps ----
    #pragma unroll
    for (int ks = 0; ks < 8; ks++) {
        const int k0 = ks * 16;
        uint32_t a[4];
        ldsm_x4(a, uA + (a_row * K2PAD + k0 + a_kof) * 2);
        #pragma unroll
        for (int np = 0; np < 4; np++) {
            const int n0 = nside + np * 16;
            uint32_t w[4];
            ldsm_x4(w, uW2 + ((n0 + w_rof) * K2PAD + k0 + w_kof) * 2);
            mma16816(acc[2*np],   a, w[0], w[1]);
            mma16816(acc[2*np+1], a, w[2], w[3]);
        }
    }

    // ---- epilogue 2: relu(+b2) . W3, reduce to scores ----
    {
        float pl = 0.f, ph = 0.f;
        #pragma unroll
        for (int nt = 0; nt < 8; nt++) {
            const int c = nside + nt * 8 + (lane & 3) * 2;
            pl = fmaf(fmaxf(acc[nt][0] + sB2[c],     0.f), sW3[c],     pl);
            pl = fmaf(fmaxf(acc[nt][1] + sB2[c + 1], 0.f), sW3[c + 1], pl);
            ph = fmaf(fmaxf(acc[nt][2] + sB2[c],     0.f), sW3[c],     ph);
            ph = fmaf(fmaxf(acc[nt][3] + sB2[c + 1], 0.f), sW3[c + 1], ph);
        }
        pl += __shfl_xor_sync(0xFFFFFFFF, pl, 1);
        pl += __shfl_xor_sync(0xFFFFFFFF, pl, 2);
        ph += __shfl_xor_sync(0xFFFFFFFF, ph, 1);
        ph += __shfl_xor_sync(0xFFFFFFFF, ph, 2);
        if ((lane & 3) == 0) {
            const int r = m0 + (lane >> 2);
            red[r * 2 + (wid & 1)]       = pl;
            red[(r + 8) * 2 + (wid & 1)] = ph;
        }
    }
    __syncthreads();
    if (tid < TM)
        g_scores[row0 + tid] = red[tid * 2] + red[tid * 2 + 1] + b3v;
}

// ---------------- lambda kernel: 4 blocks/batch, j split 4 ways ----------------
__global__ __launch_bounds__(256, 8)
void lambda_kernel(const int* __restrict__ labels, float* __restrict__ out)
{
    __shared__ float4 elg[NN];       // {exp(s), 1+log2(1+s), 2^label, 0}
    __shared__ float  part[256];

    const int bid   = blockIdx.x;        // 0..1023
    const int batch = bid >> 2;
    const int iq    = bid & 3;           // i-quarter
    const int tid   = threadIdx.x;       // 0..255
    const int il    = tid & 63;          // i within quarter
    const int jh    = tid >> 6;          // j-quarter 0..3

    {
        float s = g_scores[batch * NN + tid];
        int   l = labels[batch * NN + tid];
        elg[tid] = make_float4(expf(s), 1.0f + log2f(1.0f + s), exp2f((float)l), 0.f);
    }
    __syncthreads();

    const int i = iq * 64 + il;
    const float4 me = elg[i];
    const float ei = me.x, Mi = me.y, gi = me.z;

    float acc0 = 0.f, acc1 = 0.f;
    const int j0 = jh * 64;
    #pragma unroll 4
    for (int j = 0; j < 64; j += 2) {
        float4 va = elg[j0 + j];
        float4 vb = elg[j0 + j + 1];
        float sga = gi - va.z;
        float sgb = gi - vb.z;
        float ta = (sga > 0.f) ? ei : va.x;
        float tb = (sgb > 0.f) ? ei : vb.x;
        acc0 += __fdividef(sga * ta, fabsf(fmaxf(Mi, va.y)) * (ei + va.x));
        acc1 += __fdividef(sgb * tb, fabsf(fmaxf(Mi, vb.y)) * (ei + vb.x));
    }
    part[tid] = acc0 + acc1;
    __syncthreads();
    if (tid < 64)
        out[batch * NN + iq * 64 + tid] =
            0.5f * (part[tid] + part[tid + 64] + part[tid + 128] + part[tid + 192]);
}

extern "C" void kernel_launch(void* const* d_in, const int* in_sizes, int n_in,
                              void* d_out, int out_size)
{
    const float* feat   = (const float*)d_in[0];
    const int*   labels = (const int*)d_in[1];
    const float* W1 = (const float*)d_in[2];
    const float* b1 = (const float*)d_in[3];
    const float* W2 = (const float*)d_in[4];
    const float* b2 = (const float*)d_in[5];
    const float* W3 = (const float*)d_in[6];
    const float* b3 = (const float*)d_in[7];
    float* out = (float*)d_out;

    static bool attr_set = false;
    if (!attr_set) {
        cudaFuncSetAttribute(mlp_mma, cudaFuncAttributeMaxDynamicSharedMemorySize,
                             (int)SMEM_BYTES);
        attr_set = true;
    }

    prep_w<<<(152 * 32 + 128 * 32 + 255) / 256, 256>>>(W1, W2);
    mlp_mma<<<ROWS / TM, NT, SMEM_BYTES>>>(feat, b1, b2, W3, b3);
    lambda_kernel<<<4 * BB, 256>>>(labels, out);
}

// round 12
// speedup vs baseline: 1.6491x; 1.0026x over previous
#include <cuda_runtime.h>
#include <cuda_fp16.h>
#include <math.h>
#include <stdint.h>

#define BB 256
#define NN 256
#define DD 136
#define HH 128
#define ROWS (BB*NN)

#define K1PAD 152      // layer-1 K stride (304B rows -> conflict-free ldmatrix)
#define K2PAD 136      // layer-2 K stride (272B rows -> conflict-free)
#define TM    64       // rows per tile
#define NT    256      // 8 warps
#define GRID  296      // 2 CTAs x 148 SMs, all co-resident
#define NTILES (ROWS / TM)   // 1024

// ---------------- scratch globals ----------------
__device__ float g_scores[ROWS];
__device__ __align__(16) __half g_W1t[HH * K1PAD];
__device__ __align__(16) __half g_W2t[HH * K2PAD];
__device__ unsigned long long g_bar = 0ULL;   // monotonic barrier counter

// ---------------- smem layout ----------------
#define A_BYTES  (TM * K1PAD * 2)           // 19456
#define W1_BYTES (128 * K1PAD * 2)          // 38912
#define W2_BYTES (128 * K2PAD * 2)          // 34816
#define OFF_A    0
#define OFF_W1   (A_BYTES)                  // 19456
#define OFF_W2   (OFF_W1 + W1_BYTES)        // 58368
#define OFF_B1   (OFF_W2 + W2_BYTES)        // 93184
#define OFF_B2   (OFF_B1 + 512)
#define OFF_W3   (OFF_B2 + 512)
#define OFF_RED  (OFF_W3 + 512)
#define SMEM_BYTES (OFF_RED + 512)          // 95232 (x2 CTAs = 190464 < 227KB)

__device__ __forceinline__ uint32_t smem_u32(const void* p) {
    uint32_t a;
    asm("{ .reg .u64 t; cvta.to.shared.u64 t, %1; cvt.u32.u64 %0, t; }" : "=r"(a) : "l"(p));
    return a;
}
__device__ __forceinline__ void cp_async16(uint32_t dst, const void* src) {
    asm volatile("cp.async.cg.shared.global [%0], [%1], 16;" :: "r"(dst), "l"(src));
}
#define CP_COMMIT() asm volatile("cp.async.commit_group;" ::: "memory")
#define CP_WAIT0()  asm volatile("cp.async.wait_group 0;" ::: "memory")

__device__ __forceinline__ void ldsm_x4(uint32_t* r, uint32_t addr) {
    asm volatile("ldmatrix.sync.aligned.m8n8.x4.shared.b16 {%0,%1,%2,%3}, [%4];"
        : "=r"(r[0]), "=r"(r[1]), "=r"(r[2]), "=r"(r[3]) : "r"(addr));
}
__device__ __forceinline__ void mma16816(float* d, const uint32_t* a, uint32_t b0, uint32_t b1) {
    asm volatile("mma.sync.aligned.m16n8k16.row.col.f32.f16.f16.f32 "
        "{%0,%1,%2,%3}, {%4,%5,%6,%7}, {%8,%9}, {%0,%1,%2,%3};"
        : "+f"(d[0]), "+f"(d[1]), "+f"(d[2]), "+f"(d[3])
        : "r"(a[0]), "r"(a[1]), "r"(a[2]), "r"(a[3]), "r"(b0), "r"(b1));
}
__device__ __forceinline__ uint32_t pack_h2(float x, float y) {
    __half h0 = __float2half_rn(x), h1 = __float2half_rn(y);
    return ((uint32_t)__half_as_ushort(h1) << 16) | __half_as_ushort(h0);
}

// ---------------- persistent fused MLP (prep + barrier + tile loop) ----------------
__global__ __launch_bounds__(NT, 2)
void mlp_persist(const float* __restrict__ feat,
                 const float* __restrict__ W1, const float* __restrict__ b1,
                 const float* __restrict__ W2, const float* __restrict__ b2,
                 const float* __restrict__ W3, const float* __restrict__ b3)
{
    extern __shared__ char smem[];
    __half* A  = (__half*)(smem + OFF_A);
    float* sB1 = (float*)(smem + OFF_B1);
    float* sB2 = (float*)(smem + OFF_B2);
    float* sW3 = (float*)(smem + OFF_W3);
    float* red = (float*)(smem + OFF_RED);

    const int tid  = threadIdx.x;
    const int lane = tid & 31;
    const int wid  = tid >> 5;
    const int m0    = (wid >> 1) * 16;
    const int nside = (wid & 1) * 64;

    const uint32_t uA  = smem_u32(smem + OFF_A);
    const uint32_t uW1 = smem_u32(smem + OFF_W1);
    const uint32_t uW2 = smem_u32(smem + OFF_W2);

    const int a_row = m0 + (lane & 7) + ((lane >> 3) & 1) * 8;
    const int a_kof = (lane >> 4) * 8;
    const int w_rof = (lane & 7) + (lane >> 4) * 8;
    const int w_kof = ((lane >> 3) & 1) * 8;

    // ===== phase 0: weight prep (grid-strided), then global barrier =====
    for (int idx = blockIdx.x * NT + tid; idx < 152 * 32 + 128 * 32; idx += GRID * NT) {
        if (idx < 152 * 32) {
            int k = idx >> 5, nq = (idx & 31) * 4;
            float4 v = (k < DD) ? *(const float4*)(W1 + k * HH + nq)
                                : make_float4(0.f, 0.f, 0.f, 0.f);
            g_W1t[(nq + 0) * K1PAD + k] = __float2half_rn(v.x);
            g_W1t[(nq + 1) * K1PAD + k] = __float2half_rn(v.y);
            g_W1t[(nq + 2) * K1PAD + k] = __float2half_rn(v.z);
            g_W1t[(nq + 3) * K1PAD + k] = __float2half_rn(v.w);
        } else {
            int idx2 = idx - 152 * 32;
            int k = idx2 >> 5, nq = (idx2 & 31) * 4;
            float4 v = *(const float4*)(W2 + k * HH + nq);
            g_W2t[(nq + 0) * K2PAD + k] = __float2half_rn(v.x);
            g_W2t[(nq + 1) * K2PAD + k] = __float2half_rn(v.y);
            g_W2t[(nq + 2) * K2PAD + k] = __float2half_rn(v.z);
            g_W2t[(nq + 3) * K2PAD + k] = __float2half_rn(v.w);
        }
    }
    __threadfence();          // publish W writes (release)
    __syncthreads();          // whole CTA's prep done
    if (tid == 0) {
        unsigned long long old = atomicAdd(&g_bar, 1ULL);
        unsigned long long target = (old / GRID + 1ULL) * GRID;
        unsigned long long v;
        do {
            asm volatile("ld.acquire.gpu.global.u64 %0, [%1];" : "=l"(v) : "l"(&g_bar));
        } while (v < target);
    }
    __syncthreads();          // release all warps; W globally visible

    // ===== stage weights to smem ONCE =====
    {
        const char* s;
        s = (const char*)g_W1t;
        for (int i = tid; i < W1_BYTES / 16; i += NT) cp_async16(uW1 + i * 16, s + i * 16);
        s = (const char*)g_W2t;
        for (int i = tid; i < W2_BYTES / 16; i += NT) cp_async16(uW2 + i * 16, s + i * 16);
        CP_COMMIT();
    }
    if (tid < 128) { sB1[tid] = b1[tid]; sB2[tid] = b2[tid]; sW3[tid] = W3[tid]; }
    const float b3v = __ldg(b3);
    CP_WAIT0();

    // ===== persistent tile loop =====
    for (int tile = blockIdx.x; tile < NTILES; tile += GRID) {
        const long row0 = (long)tile * TM;
        __syncthreads();   // previous iteration's A reads complete

        // ---- stage features -> fp16 ----
        {
            const int r  = tid >> 2;
            const int c4 = tid & 3;
            const float* fb = feat + (row0 + r) * DD + 2 * c4;
            float2 v[17];
            #pragma unroll
            for (int it = 0; it < 17; it++) v[it] = *(const float2*)(fb + 8 * it);
            #pragma unroll
            for (int it = 0; it < 17; it++) {
                const int p = c4 + 4 * it;
                *(uint32_t*)(A + r * K1PAD + 2 * p) = pack_h2(v[it].x, v[it].y);
            }
            *(uint32_t*)(A + r * K1PAD + 2 * (68 + c4)) = 0;
            *(uint32_t*)(A + r * K1PAD + 2 * (72 + c4)) = 0;
        }
        __syncthreads();

        float acc[8][4];
        #pragma unroll
        for (int t = 0; t < 8; t++)
            #pragma unroll
            for (int q = 0; q < 4; q++) acc[t][q] = 0.f;

        // ---- layer 1: 9 ksteps ----
        #pragma unroll
        for (int ks = 0; ks < 9; ks++) {
            const int k0 = ks * 16;
            uint32_t a[4];
            ldsm_x4(a, uA + (a_row * K1PAD + k0 + a_kof) * 2);
            #pragma unroll
            for (int np = 0; np < 4; np++) {
                const int n0 = nside + np * 16;
                uint32_t w[4];
                ldsm_x4(w, uW1 + ((n0 + w_rof) * K1PAD + k0 + w_kof) * 2);
                mma16816(acc[2*np],   a, w[0], w[1]);
                mma16816(acc[2*np+1], a, w[2], w[3]);
            }
        }
        __syncthreads();

        // ---- epilogue 1: relu(+b1) -> fp16 into A, stride K2PAD ----
        {
            const int rA = m0 + (lane >> 2);
            #pragma unroll
            for (int nt = 0; nt < 8; nt++) {
                const int c = nside + nt * 8 + (lane & 3) * 2;
                float v0 = fmaxf(acc[nt][0] + sB1[c],     0.f);
                float v1 = fmaxf(acc[nt][1] + sB1[c + 1], 0.f);
                float v2 = fmaxf(acc[nt][2] + sB1[c],     0.f);
                float v3 = fmaxf(acc[nt][3] + sB1[c + 1], 0.f);
                *(uint32_t*)(A + rA * K2PAD + c)       = pack_h2(v0, v1);
                *(uint32_t*)(A + (rA + 8) * K2PAD + c) = pack_h2(v2, v3);
            }
        }
        __syncthreads();

        #pragma unroll
        for (int t = 0; t < 8; t++)
            #pragma unroll
            for (int q = 0; q < 4; q++) acc[t][q] = 0.f;

        // ---- layer 2: 8 ksteps ----
        #pragma unroll
        for (int ks = 0; ks < 8; ks++) {
            const int k0 = ks * 16;
            uint32_t a[4];
            ldsm_x4(a, uA + (a_row * K2PAD + k0 + a_kof) * 2);
            #pragma unroll
            for (int np = 0; np < 4; np++) {
                const int n0 = nside + np * 16;
                uint32_t w[4];
                ldsm_x4(w, uW2 + ((n0 + w_rof) * K2PAD + k0 + w_kof) * 2);
                mma16816(acc[2*np],   a, w[0], w[1]);
                mma16816(acc[2*np+1], a, w[2], w[3]);
            }
        }

        // ---- epilogue 2: relu(+b2) . W3, reduce to scores ----
        {
            float pl = 0.f, ph = 0.f;
            #pragma unroll
            for (int nt = 0; nt < 8; nt++) {
                const int c = nside + nt * 8 + (lane & 3) * 2;
                pl = fmaf(fmaxf(acc[nt][0] + sB2[c],     0.f), sW3[c],     pl);
                pl = fmaf(fmaxf(acc[nt][1] + sB2[c + 1], 0.f), sW3[c + 1], pl);
                ph = fmaf(fmaxf(acc[nt][2] + sB2[c],     0.f), sW3[c],     ph);
                ph = fmaf(fmaxf(acc[nt][3] + sB2[c + 1], 0.f), sW3[c + 1], ph);
            }
            pl += __shfl_xor_sync(0xFFFFFFFF, pl, 1);
            pl += __shfl_xor_sync(0xFFFFFFFF, pl, 2);
            ph += __shfl_xor_sync(0xFFFFFFFF, ph, 1);
            ph += __shfl_xor_sync(0xFFFFFFFF, ph, 2);
            if ((lane & 3) == 0) {
                const int r = m0 + (lane >> 2);
                red[r * 2 + (wid & 1)]       = pl;
                red[(r + 8) * 2 + (wid & 1)] = ph;
            }
        }
        __syncthreads();
        if (tid < TM)
            g_scores[row0 + tid] = red[tid * 2] + red[tid * 2 + 1] + b3v;
    }
}

// ---------------- lambda kernel: 4 blocks/batch, j split 4 ways ----------------
__global__ __launch_bounds__(256, 8)
void lambda_kernel(const int* __restrict__ labels, float* __restrict__ out)
{
    __shared__ float4 elg[NN];       // {exp(s), 1+log2(1+s), 2^label, 0}
    __shared__ float  part[256];

    const int bid   = blockIdx.x;        // 0..1023
    const int batch = bid >> 2;
    const int iq    = bid & 3;
    const int tid   = threadIdx.x;
    const int il    = tid & 63;
    const int jh    = tid >> 6;

    {
        float s = g_scores[batch * NN + tid];
        int   l = labels[batch * NN + tid];
        elg[tid] = make_float4(expf(s), 1.0f + log2f(1.0f + s), exp2f((float)l), 0.f);
    }
    __syncthreads();

    const int i = iq * 64 + il;
    const float4 me = elg[i];
    const float ei = me.x, Mi = me.y, gi = me.z;

    float acc0 = 0.f, acc1 = 0.f;
    const int j0 = jh * 64;
    #pragma unroll 4
    for (int j = 0; j < 64; j += 2) {
        float4 va = elg[j0 + j];
        float4 vb = elg[j0 + j + 1];
        float sga = gi - va.z;
        float sgb = gi - vb.z;
        float ta = (sga > 0.f) ? ei : va.x;
        float tb = (sgb > 0.f) ? ei : vb.x;
        acc0 += __fdividef(sga * ta, fabsf(fmaxf(Mi, va.y)) * (ei + va.x));
        acc1 += __fdividef(sgb * tb, fabsf(fmaxf(Mi, vb.y)) * (ei + vb.x));
    }
    part[tid] = acc0 + acc1;
    __syncthreads();
    if (tid < 64)
        out[batch * NN + iq * 64 + tid] =
            0.5f * (part[tid] + part[tid + 64] + part[tid + 128] + part[tid + 192]);
}

extern "C" void kernel_launch(void* const* d_in, const int* in_sizes, int n_in,
                              void* d_out, int out_size)
{
    const float* feat   = (const float*)d_in[0];
    const int*   labels = (const int*)d_in[1];
    const float* W1 = (const float*)d_in[2];
    const float* b1 = (const float*)d_in[3];
    const float* W2 = (const float*)d_in[4];
    const float* b2 = (const float*)d_in[5];
    const float* W3 = (const float*)d_in[6];
    const float* b3 = (const float*)d_in[7];
    float* out = (float*)d_out;

    static bool attr_set = false;
    if (!attr_set) {
        cudaFuncSetAttribute(mlp_persist, cudaFuncAttributeMaxDynamicSharedMemorySize,
                             (int)SMEM_BYTES);
        attr_set = true;
    }

    mlp_persist<<<GRID, NT, SMEM_BYTES>>>(feat, W1, b1, W2, b2, W3, b3);
    lambda_kernel<<<4 * BB, 256>>>(labels, out);
}

// round 13
// speedup vs baseline: 1.7552x; 1.0644x over previous
#include <cuda_runtime.h>
#include <cuda_fp16.h>
#include <math.h>
#include <stdint.h>

#define BB 256
#define NN 256
#define DD 136
#define HH 128
#define ROWS (BB*NN)

#define K1PAD 152      // layer-1 K stride (304B rows -> conflict-free ldmatrix)
#define K2PAD 136      // layer-2 K stride (272B rows -> conflict-free)
#define TM    64       // rows per tile
#define NT    256      // 8 warps
#define GRID  296      // 2 CTAs x 148 SMs, all co-resident
#define NTILES (ROWS / TM)   // 1024

// ---------------- scratch globals ----------------
__device__ __align__(16) float4 g_elg[ROWS];        // {exp(s), 1+log2(1+s), 2^label, 0}
__device__ __align__(16) __half g_W1t[HH * K1PAD];
__device__ __align__(16) __half g_W2t[HH * K2PAD];
__device__ unsigned long long g_bar = 0ULL;         // monotonic barrier counter

// ---------------- smem layout ----------------
#define A_BYTES  (TM * K1PAD * 2)           // 19456
#define W1_BYTES (128 * K1PAD * 2)          // 38912
#define W2_BYTES (128 * K2PAD * 2)          // 34816
#define OFF_A    0
#define OFF_W1   (A_BYTES)
#define OFF_W2   (OFF_W1 + W1_BYTES)
#define OFF_B1   (OFF_W2 + W2_BYTES)        // 93184
#define OFF_B2   (OFF_B1 + 512)
#define OFF_W3   (OFF_B2 + 512)
#define OFF_RED  (OFF_W3 + 512)
#define SMEM_BYTES (OFF_RED + 512)          // 95232 (x2 CTAs < 227KB)

__device__ __forceinline__ uint32_t smem_u32(const void* p) {
    uint32_t a;
    asm("{ .reg .u64 t; cvta.to.shared.u64 t, %1; cvt.u32.u64 %0, t; }" : "=r"(a) : "l"(p));
    return a;
}
__device__ __forceinline__ void cp_async16(uint32_t dst, const void* src) {
    asm volatile("cp.async.cg.shared.global [%0], [%1], 16;" :: "r"(dst), "l"(src));
}
#define CP_COMMIT() asm volatile("cp.async.commit_group;" ::: "memory")
#define CP_WAIT0()  asm volatile("cp.async.wait_group 0;" ::: "memory")

__device__ __forceinline__ void ldsm_x4(uint32_t* r, uint32_t addr) {
    asm volatile("ldmatrix.sync.aligned.m8n8.x4.shared.b16 {%0,%1,%2,%3}, [%4];"
        : "=r"(r[0]), "=r"(r[1]), "=r"(r[2]), "=r"(r[3]) : "r"(addr));
}
__device__ __forceinline__ void mma16816(float* d, const uint32_t* a, uint32_t b0, uint32_t b1) {
    asm volatile("mma.sync.aligned.m16n8k16.row.col.f32.f16.f16.f32 "
        "{%0,%1,%2,%3}, {%4,%5,%6,%7}, {%8,%9}, {%0,%1,%2,%3};"
        : "+f"(d[0]), "+f"(d[1]), "+f"(d[2]), "+f"(d[3])
        : "r"(a[0]), "r"(a[1]), "r"(a[2]), "r"(a[3]), "r"(b0), "r"(b1));
}
__device__ __forceinline__ uint32_t pack_h2(float x, float y) {
    __half h0 = __float2half_rn(x), h1 = __float2half_rn(y);
    return ((uint32_t)__half_as_ushort(h1) << 16) | __half_as_ushort(h0);
}

// ---------------- persistent fused MLP (prep + barrier + pipelined tile loop) ----------------
__global__ __launch_bounds__(NT, 2)
void mlp_persist(const float* __restrict__ feat, const int* __restrict__ labels,
                 const float* __restrict__ W1, const float* __restrict__ b1,
                 const float* __restrict__ W2, const float* __restrict__ b2,
                 const float* __restrict__ W3, const float* __restrict__ b3)
{
    extern __shared__ char smem[];
    __half* A  = (__half*)(smem + OFF_A);
    float* sB1 = (float*)(smem + OFF_B1);
    float* sB2 = (float*)(smem + OFF_B2);
    float* sW3 = (float*)(smem + OFF_W3);
    float* red = (float*)(smem + OFF_RED);

    const int tid  = threadIdx.x;
    const int lane = tid & 31;
    const int wid  = tid >> 5;
    const int m0    = (wid >> 1) * 16;
    const int nside = (wid & 1) * 64;

    const uint32_t uA  = smem_u32(smem + OFF_A);
    const uint32_t uW1 = smem_u32(smem + OFF_W1);
    const uint32_t uW2 = smem_u32(smem + OFF_W2);

    const int a_row = m0 + (lane & 7) + ((lane >> 3) & 1) * 8;
    const int a_kof = (lane >> 4) * 8;
    const int w_rof = (lane & 7) + (lane >> 4) * 8;
    const int w_kof = ((lane >> 3) & 1) * 8;

    // ===== phase 0: weight prep (grid-strided), then global barrier =====
    for (int idx = blockIdx.x * NT + tid; idx < 152 * 32 + 128 * 32; idx += GRID * NT) {
        if (idx < 152 * 32) {
            int k = idx >> 5, nq = (idx & 31) * 4;
            float4 v = (k < DD) ? *(const float4*)(W1 + k * HH + nq)
                                : make_float4(0.f, 0.f, 0.f, 0.f);
            g_W1t[(nq + 0) * K1PAD + k] = __float2half_rn(v.x);
            g_W1t[(nq + 1) * K1PAD + k] = __float2half_rn(v.y);
            g_W1t[(nq + 2) * K1PAD + k] = __float2half_rn(v.z);
            g_W1t[(nq + 3) * K1PAD + k] = __float2half_rn(v.w);
        } else {
            int idx2 = idx - 152 * 32;
            int k = idx2 >> 5, nq = (idx2 & 31) * 4;
            float4 v = *(const float4*)(W2 + k * HH + nq);
            g_W2t[(nq + 0) * K2PAD + k] = __float2half_rn(v.x);
            g_W2t[(nq + 1) * K2PAD + k] = __float2half_rn(v.y);
            g_W2t[(nq + 2) * K2PAD + k] = __float2half_rn(v.z);
            g_W2t[(nq + 3) * K2PAD + k] = __float2half_rn(v.w);
        }
    }
    __threadfence();
    __syncthreads();
    if (tid == 0) {
        unsigned long long old = atomicAdd(&g_bar, 1ULL);
        unsigned long long target = (old / GRID + 1ULL) * GRID;
        unsigned long long v;
        do {
            asm volatile("ld.acquire.gpu.global.u64 %0, [%1];" : "=l"(v) : "l"(&g_bar));
        } while (v < target);
    }
    __syncthreads();

    // ===== stage weights to smem ONCE =====
    {
        const char* s;
        s = (const char*)g_W1t;
        for (int i = tid; i < W1_BYTES / 16; i += NT) cp_async16(uW1 + i * 16, s + i * 16);
        s = (const char*)g_W2t;
        for (int i = tid; i < W2_BYTES / 16; i += NT) cp_async16(uW2 + i * 16, s + i * 16);
        CP_COMMIT();
    }
    if (tid < 128) { sB1[tid] = b1[tid]; sB2[tid] = b2[tid]; sW3[tid] = W3[tid]; }
    const float b3v = __ldg(b3);
    CP_WAIT0();
    __syncthreads();    // W + biases resident before first tile

    // ===== pipelined persistent tile loop =====
    const int r  = tid >> 2;        // staging row 0..63
    const int c4 = tid & 3;         // staging pair-lane
    float2 v[17];
    {   // initial prefetch
        const float* fb = feat + ((long)blockIdx.x * TM + r) * DD + 2 * c4;
        #pragma unroll
        for (int it = 0; it < 17; it++) v[it] = *(const float2*)(fb + 8 * it);
    }

    for (int tile = blockIdx.x; tile < NTILES; tile += GRID) {
        const long row0 = (long)tile * TM;

        // ---- store prefetched features -> fp16 A ----
        #pragma unroll
        for (int it = 0; it < 17; it++) {
            const int p = c4 + 4 * it;
            *(uint32_t*)(A + r * K1PAD + 2 * p) = pack_h2(v[it].x, v[it].y);
        }
        *(uint32_t*)(A + r * K1PAD + 2 * (68 + c4)) = 0;
        *(uint32_t*)(A + r * K1PAD + 2 * (72 + c4)) = 0;
        __syncthreads();

        // ---- prefetch next tile's features (overlaps MMA below) ----
        {
            const int nxt = tile + GRID;
            if (nxt < NTILES) {
                const float* fb = feat + ((long)nxt * TM + r) * DD + 2 * c4;
                #pragma unroll
                for (int it = 0; it < 17; it++) v[it] = *(const float2*)(fb + 8 * it);
            }
        }

        float acc[8][4];
        #pragma unroll
        for (int t = 0; t < 8; t++)
            #pragma unroll
            for (int q = 0; q < 4; q++) acc[t][q] = 0.f;

        // ---- layer 1: 9 ksteps ----
        #pragma unroll
        for (int ks = 0; ks < 9; ks++) {
            const int k0 = ks * 16;
            uint32_t a[4];
            ldsm_x4(a, uA + (a_row * K1PAD + k0 + a_kof) * 2);
            #pragma unroll
            for (int np = 0; np < 4; np++) {
                const int n0 = nside + np * 16;
                uint32_t w[4];
                ldsm_x4(w, uW1 + ((n0 + w_rof) * K1PAD + k0 + w_kof) * 2);
                mma16816(acc[2*np],   a, w[0], w[1]);
                mma16816(acc[2*np+1], a, w[2], w[3]);
            }
        }
        __syncthreads();

        // ---- epilogue 1: relu(+b1) -> fp16 into A, stride K2PAD ----
        {
            const int rA = m0 + (lane >> 2);
            #pragma unroll
            for (int nt = 0; nt < 8; nt++) {
                const int c = nside + nt * 8 + (lane & 3) * 2;
                float v0 = fmaxf(acc[nt][0] + sB1[c],     0.f);
                float v1 = fmaxf(acc[nt][1] + sB1[c + 1], 0.f);
                float v2 = fmaxf(acc[nt][2] + sB1[c],     0.f);
                float v3 = fmaxf(acc[nt][3] + sB1[c + 1], 0.f);
                *(uint32_t*)(A + rA * K2PAD + c)       = pack_h2(v0, v1);
                *(uint32_t*)(A + (rA + 8) * K2PAD + c) = pack_h2(v2, v3);
            }
        }
        __syncthreads();

        #pragma unroll
        for (int t = 0; t < 8; t++)
            #pragma unroll
            for (int q = 0; q < 4; q++) acc[t][q] = 0.f;

        // ---- layer 2: 8 ksteps ----
        #pragma unroll
        for (int ks = 0; ks < 8; ks++) {
            const int k0 = ks * 16;
            uint32_t a[4];
            ldsm_x4(a, uA + (a_row * K2PAD + k0 + a_kof) * 2);
            #pragma unroll
            for (int np = 0; np < 4; np++) {
                const int n0 = nside + np * 16;
                uint32_t w[4];
                ldsm_x4(w, uW2 + ((n0 + w_rof) * K2PAD + k0 + w_kof) * 2);
                mma16816(acc[2*np],   a, w[0], w[1]);
                mma16816(acc[2*np+1], a, w[2], w[3]);
            }
        }

        // ---- epilogue 2: relu(+b2) . W3, reduce, fused elg write ----
        {
            float pl = 0.f, ph = 0.f;
            #pragma unroll
            for (int nt = 0; nt < 8; nt++) {
                const int c = nside + nt * 8 + (lane & 3) * 2;
                pl = fmaf(fmaxf(acc[nt][0] + sB2[c],     0.f), sW3[c],     pl);
                pl = fmaf(fmaxf(acc[nt][1] + sB2[c + 1], 0.f), sW3[c + 1], pl);
                ph = fmaf(fmaxf(acc[nt][2] + sB2[c],     0.f), sW3[c],     ph);
                ph = fmaf(fmaxf(acc[nt][3] + sB2[c + 1], 0.f), sW3[c + 1], ph);
            }
            pl += __shfl_xor_sync(0xFFFFFFFF, pl, 1);
            pl += __shfl_xor_sync(0xFFFFFFFF, pl, 2);
            ph += __shfl_xor_sync(0xFFFFFFFF, ph, 1);
            ph += __shfl_xor_sync(0xFFFFFFFF, ph, 2);
            if ((lane & 3) == 0) {
                const int rr = m0 + (lane >> 2);
                red[rr * 2 + (wid & 1)]       = pl;
                red[(rr + 8) * 2 + (wid & 1)] = ph;
            }
        }
        __syncthreads();
        if (tid < TM) {
            float s = red[tid * 2] + red[tid * 2 + 1] + b3v;
            int   l = labels[row0 + tid];
            float e = __expf(s);
            float M = 1.0f + __log2f(1.0f + s);
            float g = __int_as_float((l + 127) << 23);   // 2^l exactly, l in [0,5)
            g_elg[row0 + tid] = make_float4(e, M, g, 0.f);
        }
    }
}

// ---------------- lambda kernel: 8 blocks/batch, prologue precomputed ----------------
__global__ __launch_bounds__(256, 8)
void lambda_kernel(float* __restrict__ out)
{
    __shared__ float4 elg[NN];
    __shared__ float  part[256];

    const int bid   = blockIdx.x;        // 0..2047
    const int batch = bid >> 3;
    const int io    = bid & 7;           // i-octant (32 rows)
    const int tid   = threadIdx.x;
    const int il    = tid & 31;
    const int jh    = tid >> 5;          // j-octant 0..7

    elg[tid] = g_elg[batch * NN + tid];
    __syncthreads();

    const int i = io * 32 + il;
    const float4 me = elg[i];
    const float ei = me.x, Mi = me.y, gi = me.z;

    float acc0 = 0.f, acc1 = 0.f;
    const int j0 = jh * 32;
    #pragma unroll 4
    for (int j = 0; j < 32; j += 2) {
        float4 va = elg[j0 + j];
        float4 vb = elg[j0 + j + 1];
        float sga = gi - va.z;
        float sgb = gi - vb.z;
        float ta = (sga > 0.f) ? ei : va.x;
        float tb = (sgb > 0.f) ? ei : vb.x;
        acc0 += __fdividef(sga * ta, fabsf(fmaxf(Mi, va.y)) * (ei + va.x));
        acc1 += __fdividef(sgb * tb, fabsf(fmaxf(Mi, vb.y)) * (ei + vb.x));
    }
    part[tid] = acc0 + acc1;
    __syncthreads();
    if (tid < 32) {
        float s = 0.f;
        #pragma unroll
        for (int k = 0; k < 8; k++) s += part[tid + 32 * k];
        out[batch * NN + io * 32 + tid] = 0.5f * s;
    }
}

extern "C" void kernel_launch(void* const* d_in, const int* in_sizes, int n_in,
                              void* d_out, int out_size)
{
    const float* feat   = (const float*)d_in[0];
    const int*   labels = (const int*)d_in[1];
    const float* W1 = (const float*)d_in[2];
    const float* b1 = (const float*)d_in[3];
    const float* W2 = (const float*)d_in[4];
    const float* b2 = (const float*)d_in[5];
    const float* W3 = (const float*)d_in[6];
    const float* b3 = (const float*)d_in[7];
    float* out = (float*)d_out;

    static bool attr_set = false;
    if (!attr_set) {
        cudaFuncSetAttribute(mlp_persist, cudaFuncAttributeMaxDynamicSharedMemorySize,
                             (int)SMEM_BYTES);
        attr_set = true;
    }

    mlp_persist<<<GRID, NT, SMEM_BYTES>>>(feat, labels, W1, b1, W2, b2, W3, b3);
    lambda_kernel<<<8 * BB, 256>>>(out);
}